// round 2
// baseline (speedup 1.0000x reference)
#include <cuda_runtime.h>
#include <math.h>

// Problem constants
#define BB 4
#define TT 2048
#define CC 1024
#define HH 16
#define DD 64
#define BT (BB*TT)          // 8192 rows

// ---------------------------------------------------------------------------
// Scratch (device globals; no allocations allowed in kernel_launch)
// ---------------------------------------------------------------------------
__device__ float g_qkv[(size_t)BT * 3 * CC];        // [B*T, 3C]
__device__ float g_q[(size_t)BB * HH * TT * DD];    // [B,H,T,D]
__device__ float g_k[(size_t)BB * HH * TT * DD];
__device__ float g_v[(size_t)BB * HH * TT * DD];
__device__ float g_y[(size_t)BT * CC];              // attention output [B*T, C]
__device__ float g_cos[HH * 32];                    // NOTE: indexed by HEAD, not position
__device__ float g_sin[HH * 32];

// ---------------------------------------------------------------------------
// RoPE cache: the reference calls _rope_cache(x.shape[1]) where x is (B,H,T,D),
// so n_pos = N_HEAD = 16 and the cos/sin broadcast over the HEAD axis.
// Angle = h * theta_i  (head index, NOT token position).
// theta formed in fp32 like the reference, angle in fp32, sincos in double.
// ---------------------------------------------------------------------------
__global__ void __launch_bounds__(256) rope_cache_kernel() {
    int idx = blockIdx.x * blockDim.x + threadIdx.x;
    if (idx >= HH * 32) return;
    int h = idx >> 5;
    int i = idx & 31;
    float theta = (float)pow(10000.0, -((double)(2 * i)) / 64.0);
    float ang = (float)h * theta;           // fp32 rounding like the reference
    double a = (double)ang;
    double sv, cv;
    sincos(a, &sv, &cv);
    g_cos[idx] = (float)cv;
    g_sin[idx] = (float)sv;
}

// ---------------------------------------------------------------------------
// FP32 SGEMM: C[M,N] = A[M,K] @ B[K,N] + bias[N]
// BM=BN=128, BK=16, 256 threads, 8x8 per-thread micro-tile.
// All dims are multiples of tile sizes (no bounds checks needed).
// ---------------------------------------------------------------------------
template<int M, int N, int K>
__device__ __forceinline__ void sgemm_body(
    const float* __restrict__ A, const float* __restrict__ Bm,
    const float* __restrict__ bias, float* __restrict__ Cm)
{
    constexpr int BM = 128, BN = 128, BK = 16, TM = 8, TN = 8;
    __shared__ float As[BK][BM];   // A tile, transposed: [k][m]
    __shared__ float Bs[BK][BN];   // B tile: [k][n]

    const int tid = threadIdx.x;
    const int tr = tid >> 4;       // 0..15
    const int tc = tid & 15;       // 0..15
    const int rowBase = blockIdx.y * BM;
    const int colBase = blockIdx.x * BN;

    const float* Ap = A + (size_t)rowBase * K;
    const float* Bp = Bm + colBase;

    float acc[TM][TN];
#pragma unroll
    for (int i = 0; i < TM; i++)
#pragma unroll
        for (int j = 0; j < TN; j++) acc[i][j] = 0.0f;

    for (int k0 = 0; k0 < K; k0 += BK) {
        // Load A tile (128x16) as float4 along K, store transposed.
#pragma unroll
        for (int it = 0; it < 2; it++) {
            int li = tid + it * 256;               // 0..511
            int r  = li >> 2;                      // 0..127
            int kk = (li & 3) << 2;                // 0,4,8,12
            float4 va = *(const float4*)(Ap + (size_t)r * K + k0 + kk);
            As[kk + 0][r] = va.x;
            As[kk + 1][r] = va.y;
            As[kk + 2][r] = va.z;
            As[kk + 3][r] = va.w;
            // Load B tile (16x128) coalesced.
            int rb = li >> 5;                      // 0..15
            int cb = (li & 31) << 2;               // 0..124
            *(float4*)(&Bs[rb][cb]) = *(const float4*)(Bp + (size_t)(k0 + rb) * N + cb);
        }
        __syncthreads();

#pragma unroll
        for (int k = 0; k < BK; k++) {
            float rm[TM], rn[TN];
            *(float4*)(rm)     = *(const float4*)(&As[k][tr * TM]);
            *(float4*)(rm + 4) = *(const float4*)(&As[k][tr * TM + 4]);
            *(float4*)(rn)     = *(const float4*)(&Bs[k][tc * TN]);
            *(float4*)(rn + 4) = *(const float4*)(&Bs[k][tc * TN + 4]);
#pragma unroll
            for (int i = 0; i < TM; i++)
#pragma unroll
                for (int j = 0; j < TN; j++)
                    acc[i][j] += rm[i] * rn[j];
        }
        __syncthreads();
    }

    // Epilogue: add bias, write out.
#pragma unroll
    for (int i = 0; i < TM; i++) {
        size_t r = (size_t)rowBase + tr * TM + i;
#pragma unroll
        for (int j = 0; j < TN; j += 4) {
            int c = colBase + tc * TN + j;
            float4 bv = *(const float4*)(bias + c);
            float4 o;
            o.x = acc[i][j + 0] + bv.x;
            o.y = acc[i][j + 1] + bv.y;
            o.z = acc[i][j + 2] + bv.z;
            o.w = acc[i][j + 3] + bv.w;
            *(float4*)(Cm + r * N + c) = o;
        }
    }
}

__global__ void __launch_bounds__(256) qkv_gemm_kernel(
    const float* __restrict__ x, const float* __restrict__ W,
    const float* __restrict__ b)
{
    sgemm_body<BT, 3 * CC, CC>(x, W, b, g_qkv);
}

__global__ void __launch_bounds__(256) proj_gemm_kernel(
    const float* __restrict__ W, const float* __restrict__ b,
    float* __restrict__ out)
{
    sgemm_body<BT, CC, CC>(g_y, W, b, out);
}

// ---------------------------------------------------------------------------
// RoPE apply + split qkv into q/k/v with layout [B,H,T,D].
// Rotation angle indexed by HEAD (matches reference broadcast).
// ---------------------------------------------------------------------------
__global__ void __launch_bounds__(256) rope_split_kernel() {
    int idx = blockIdx.x * blockDim.x + threadIdx.x;   // < B*T*H*32 = 4194304
    int i = idx & 31;                 // pair index within head
    int h = (idx >> 5) & (HH - 1);
    int t = (idx >> 9) & (TT - 1);
    int b = idx >> 20;

    float c = g_cos[(h << 5) + i];    // head-indexed!
    float s = g_sin[(h << 5) + i];

    const float* p = g_qkv + ((size_t)(b * TT + t)) * (3 * CC) + h * DD + 2 * i;
    float2 q = *(const float2*)(p);
    float2 k = *(const float2*)(p + CC);
    float2 v = *(const float2*)(p + 2 * CC);

    float2 qo = { q.x * c - q.y * s, q.y * c + q.x * s };
    float2 ko = { k.x * c - k.y * s, k.y * c + k.x * s };

    size_t o = ((size_t)((b * HH + h) * TT + t)) * DD + 2 * i;
    *(float2*)(g_q + o) = qo;
    *(float2*)(g_k + o) = ko;
    *(float2*)(g_v + o) = v;
}

// ---------------------------------------------------------------------------
// FP32 flash attention, causal. One block per (bh, q-tile of 64).
// BQ=64, BKEY=32. 256 threads: thread (tr=tid/16, tc=tid%16).
//   S gemm:  thread computes 4 q-rows x 2 k-cols
//   PV gemm: thread computes 4 q-rows x 4 out-dims
// Row groups = 16 consecutive lanes -> width-16 xor shuffles for reductions.
// Static smem: 41.6 KB.
// ---------------------------------------------------------------------------
__global__ void __launch_bounds__(256) flash_kernel() {
    __shared__ float Qs[64][65];   // [qrow][d]
    __shared__ float Ks[32][65];   // [kcol][d]
    __shared__ float Ps[64][33];   // [qrow][kcol]
    __shared__ float Vs[32][64];   // [kcol][d]

    const int tid = threadIdx.x;
    const int iq = blockIdx.x;     // q tile (0..31)
    const int bh = blockIdx.y;     // b*H+h  (0..63)
    const int tr = tid >> 4;       // 0..15
    const int tc = tid & 15;       // 0..15

    const float* qp = g_q + ((size_t)bh * TT + iq * 64) * DD;
    const float* kp = g_k + (size_t)bh * TT * DD;
    const float* vp = g_v + (size_t)bh * TT * DD;

    // Load Q tile (64x64)
#pragma unroll
    for (int it = 0; it < 4; it++) {
        int li = tid + it * 256;       // 0..1023
        int r  = li >> 4;
        int d4 = (li & 15) << 2;
        float4 v = *(const float4*)(qp + (size_t)r * DD + d4);
        Qs[r][d4 + 0] = v.x; Qs[r][d4 + 1] = v.y;
        Qs[r][d4 + 2] = v.z; Qs[r][d4 + 3] = v.w;
    }

    float m_i[4], l_i[4], O[4][4];
#pragma unroll
    for (int i = 0; i < 4; i++) {
        m_i[i] = -1e30f; l_i[i] = 0.0f;
#pragma unroll
        for (int j = 0; j < 4; j++) O[i][j] = 0.0f;
    }
    __syncthreads();

    const int nkt = 2 * iq + 2;   // key tiles of 32 covering [0, (iq+1)*64)
    for (int kt = 0; kt < nkt; kt++) {
        const float* kpt = kp + (size_t)kt * 32 * DD;
        const float* vpt = vp + (size_t)kt * 32 * DD;
#pragma unroll
        for (int it = 0; it < 2; it++) {
            int li = tid + it * 256;   // 0..511
            int r  = li >> 4;          // 0..31
            int d4 = (li & 15) << 2;
            float4 kv = *(const float4*)(kpt + (size_t)r * DD + d4);
            Ks[r][d4 + 0] = kv.x; Ks[r][d4 + 1] = kv.y;
            Ks[r][d4 + 2] = kv.z; Ks[r][d4 + 3] = kv.w;
            *(float4*)(&Vs[r][d4]) = *(const float4*)(vpt + (size_t)r * DD + d4);
        }
        __syncthreads();

        // ---- S = Q K^T  (4x2 per thread) ----
        float s00 = 0.f, s01 = 0.f, s10 = 0.f, s11 = 0.f;
        float s20 = 0.f, s21 = 0.f, s30 = 0.f, s31 = 0.f;
        const int r0 = tr * 4;
        const int c0 = tc * 2;
#pragma unroll 16
        for (int d = 0; d < 64; d++) {
            float rm0 = Qs[r0 + 0][d];
            float rm1 = Qs[r0 + 1][d];
            float rm2 = Qs[r0 + 2][d];
            float rm3 = Qs[r0 + 3][d];
            float rn0 = Ks[c0 + 0][d];
            float rn1 = Ks[c0 + 1][d];
            s00 += rm0 * rn0; s01 += rm0 * rn1;
            s10 += rm1 * rn0; s11 += rm1 * rn1;
            s20 += rm2 * rn0; s21 += rm2 * rn1;
            s30 += rm3 * rn0; s31 += rm3 * rn1;
        }
        float sarr[4][2] = {{s00, s01}, {s10, s11}, {s20, s21}, {s30, s31}};

        // ---- scale + causal mask + online softmax ----
        const int qbase = iq * 64 + r0;
        const int kbase = kt * 32 + c0;
#pragma unroll
        for (int i = 0; i < 4; i++) {
#pragma unroll
            for (int jj = 0; jj < 2; jj++) {
                float v = sarr[i][jj] * 0.125f;
                if (kbase + jj > qbase + i) v = -1e30f;
                sarr[i][jj] = v;
            }
        }
#pragma unroll
        for (int i = 0; i < 4; i++) {
            float mx = fmaxf(sarr[i][0], sarr[i][1]);
#pragma unroll
            for (int off = 8; off > 0; off >>= 1)
                mx = fmaxf(mx, __shfl_xor_sync(0xffffffffu, mx, off, 16));
            float mnew  = fmaxf(m_i[i], mx);
            float alpha = __expf(m_i[i] - mnew);
            float p0 = __expf(sarr[i][0] - mnew);
            float p1 = __expf(sarr[i][1] - mnew);
            float rs = p0 + p1;
#pragma unroll
            for (int off = 8; off > 0; off >>= 1)
                rs += __shfl_xor_sync(0xffffffffu, rs, off, 16);
            l_i[i] = l_i[i] * alpha + rs;
            m_i[i] = mnew;
            O[i][0] *= alpha; O[i][1] *= alpha;
            O[i][2] *= alpha; O[i][3] *= alpha;
            Ps[r0 + i][c0 + 0] = p0;
            Ps[r0 + i][c0 + 1] = p1;
        }
        __syncthreads();

        // ---- O += P V  (4 rows x 4 dims per thread) ----
        const int dc = tc * 4;
#pragma unroll 8
        for (int kk = 0; kk < 32; kk++) {
            float4 rv = *(const float4*)(&Vs[kk][dc]);
            float p0v = Ps[r0 + 0][kk];
            float p1v = Ps[r0 + 1][kk];
            float p2v = Ps[r0 + 2][kk];
            float p3v = Ps[r0 + 3][kk];
            O[0][0] += p0v * rv.x; O[0][1] += p0v * rv.y; O[0][2] += p0v * rv.z; O[0][3] += p0v * rv.w;
            O[1][0] += p1v * rv.x; O[1][1] += p1v * rv.y; O[1][2] += p1v * rv.z; O[1][3] += p1v * rv.w;
            O[2][0] += p2v * rv.x; O[2][1] += p2v * rv.y; O[2][2] += p2v * rv.z; O[2][3] += p2v * rv.w;
            O[3][0] += p3v * rv.x; O[3][1] += p3v * rv.y; O[3][2] += p3v * rv.z; O[3][3] += p3v * rv.w;
        }
        __syncthreads();
    }

    // ---- epilogue: normalize, write y[B,T,C] with head concatenation ----
    const int b = bh >> 4;
    const int h = bh & 15;
#pragma unroll
    for (int i = 0; i < 4; i++) {
        int qrow = iq * 64 + tr * 4 + i;
        float inv = 1.0f / l_i[i];
        float4 o;
        o.x = O[i][0] * inv; o.y = O[i][1] * inv;
        o.z = O[i][2] * inv; o.w = O[i][3] * inv;
        *(float4*)(g_y + ((size_t)(b * TT + qrow)) * CC + h * DD + tc * 4) = o;
    }
}

// ---------------------------------------------------------------------------
// Launch
// ---------------------------------------------------------------------------
extern "C" void kernel_launch(void* const* d_in, const int* in_sizes, int n_in,
                              void* d_out, int out_size) {
    const float* x      = (const float*)d_in[0];
    const float* W_attn = (const float*)d_in[1];
    const float* b_attn = (const float*)d_in[2];
    const float* W_proj = (const float*)d_in[3];
    const float* b_proj = (const float*)d_in[4];
    float* out = (float*)d_out;

    // RoPE tables (cheap; recomputed each launch for determinism)
    rope_cache_kernel<<<2, 256>>>();

    // QKV projection: [8192,1024] @ [1024,3072] + bias
    qkv_gemm_kernel<<<dim3((3 * CC) / 128, BT / 128), 256>>>(x, W_attn, b_attn);

    // RoPE + split into q/k/v [B,H,T,D]
    rope_split_kernel<<<(BB * TT * HH * 32) / 256, 256>>>();

    // Causal flash attention
    flash_kernel<<<dim3(TT / 64, BB * HH), 256>>>();

    // Output projection: [8192,1024] @ [1024,1024] + bias
    proj_gemm_kernel<<<dim3(CC / 128, BT / 128), 256>>>(W_proj, b_proj, out);
}

// round 3
// speedup vs baseline: 1.6027x; 1.6027x over previous
#include <cuda_runtime.h>
#include <math.h>
#include <stdint.h>

// Problem constants
#define BB 4
#define TT 2048
#define CC 1024
#define HH 16
#define DD 64
#define BT (BB*TT)          // 8192 rows

// ---------------------------------------------------------------------------
// Scratch (device globals; no allocations allowed in kernel_launch)
// ---------------------------------------------------------------------------
__device__ float g_qkv[(size_t)BT * 3 * CC];        // [B*T, 3C]
__device__ float g_q[(size_t)BB * HH * TT * DD];    // [B,H,T,D]
__device__ float g_k[(size_t)BB * HH * TT * DD];
__device__ float g_v[(size_t)BB * HH * TT * DD];
__device__ float g_y[(size_t)BT * CC];              // attention output [B*T, C]
__device__ float g_cos[HH * 32];                    // indexed by HEAD (reference quirk)
__device__ float g_sin[HH * 32];

// ---------------------------------------------------------------------------
// RoPE cache: reference broadcasts cos/sin over the HEAD axis (n_pos = N_HEAD).
// Angle = h * theta_i. theta/angle formed in fp32, sincos in double.
// ---------------------------------------------------------------------------
__global__ void __launch_bounds__(256) rope_cache_kernel() {
    int idx = blockIdx.x * blockDim.x + threadIdx.x;
    if (idx >= HH * 32) return;
    int h = idx >> 5;
    int i = idx & 31;
    float theta = (float)pow(10000.0, -((double)(2 * i)) / 64.0);
    float ang = (float)h * theta;
    double sv, cv;
    sincos((double)ang, &sv, &cv);
    g_cos[idx] = (float)cv;
    g_sin[idx] = (float)sv;
}

// ---------------------------------------------------------------------------
// TF32 tensor-core GEMM: C[M,N] = A[M,K] @ B[K,N] + bias[N]
// BM=BN=128, BK=32. 256 threads = 8 warps in 4x2 grid; warp tile 32x64.
// mma.sync.aligned.m16n8k8.row.col.f32.tf32.tf32.f32, fp32 accumulate.
// Inputs rounded to tf32 with cvt.rna at the G2S stage.
// ---------------------------------------------------------------------------
__device__ __forceinline__ uint32_t f2tf32(float x) {
    uint32_t r;
    asm("cvt.rna.tf32.f32 %0, %1;" : "=r"(r) : "f"(x));
    return r;
}

__device__ __forceinline__ void mma_tf32(
    float& d0, float& d1, float& d2, float& d3,
    uint32_t a0, uint32_t a1, uint32_t a2, uint32_t a3,
    uint32_t b0, uint32_t b1)
{
    asm volatile(
        "mma.sync.aligned.m16n8k8.row.col.f32.tf32.tf32.f32 "
        "{%0,%1,%2,%3}, {%4,%5,%6,%7}, {%8,%9}, {%0,%1,%2,%3};"
        : "+f"(d0), "+f"(d1), "+f"(d2), "+f"(d3)
        : "r"(a0), "r"(a1), "r"(a2), "r"(a3), "r"(b0), "r"(b1));
}

template<int K, int N>
__device__ __forceinline__ void tf32_gemm_body(
    const float* __restrict__ A, const float* __restrict__ Bm,
    const float* __restrict__ bias, float* __restrict__ Cm)
{
    constexpr int BM = 128, BN = 128, BK = 32;
    constexpr int AST = BK + 4;    // 36: a-frag LDS banks (4g + t4) all distinct
    constexpr int BST = BN + 8;    // 136: b-frag LDS banks (8k + g) all distinct
    __shared__ uint32_t As[BM * AST];
    __shared__ uint32_t Bs[BK * BST];

    const int tid  = threadIdx.x;
    const int lane = tid & 31;
    const int warp = tid >> 5;
    const int wm = warp >> 1;          // 0..3  (M direction, 32 rows each)
    const int wn = warp & 1;           // 0..1  (N direction, 64 cols each)
    const int g  = lane >> 2;          // 0..7
    const int t4 = lane & 3;           // 0..3
    const int rowBase = blockIdx.y * BM;
    const int colBase = blockIdx.x * BN;

    const float* Ap = A + (size_t)rowBase * K;
    const float* Bp = Bm + colBase;

    float acc[2][8][4];
#pragma unroll
    for (int i = 0; i < 2; i++)
#pragma unroll
        for (int j = 0; j < 8; j++)
#pragma unroll
            for (int q = 0; q < 4; q++) acc[i][j][q] = 0.0f;

    for (int k0 = 0; k0 < K; k0 += BK) {
        // A tile 128x32: coalesced float4 along K, row-major in smem (+tf32 round)
#pragma unroll
        for (int it = 0; it < 4; it++) {
            int li = tid + it * 256;           // 0..1023
            int r  = li >> 3;                  // 0..127
            int kk = (li & 7) << 2;            // 0..28
            float4 v = *(const float4*)(Ap + (size_t)r * K + k0 + kk);
            uint32_t* dst = &As[r * AST + kk];
            dst[0] = f2tf32(v.x); dst[1] = f2tf32(v.y);
            dst[2] = f2tf32(v.z); dst[3] = f2tf32(v.w);
        }
        // B tile 32x128: coalesced float4 along N
#pragma unroll
        for (int it = 0; it < 4; it++) {
            int li = tid + it * 256;
            int r  = li >> 5;                  // 0..31
            int c  = (li & 31) << 2;           // 0..124
            float4 v = *(const float4*)(Bp + (size_t)(k0 + r) * N + c);
            uint32_t* dst = &Bs[r * BST + c];
            dst[0] = f2tf32(v.x); dst[1] = f2tf32(v.y);
            dst[2] = f2tf32(v.z); dst[3] = f2tf32(v.w);
        }
        __syncthreads();

#pragma unroll
        for (int ks = 0; ks < BK; ks += 8) {
            uint32_t af[2][4];
#pragma unroll
            for (int i = 0; i < 2; i++) {
                int m = wm * 32 + i * 16 + g;
                af[i][0] = As[m * AST + ks + t4];
                af[i][1] = As[(m + 8) * AST + ks + t4];
                af[i][2] = As[m * AST + ks + t4 + 4];
                af[i][3] = As[(m + 8) * AST + ks + t4 + 4];
            }
#pragma unroll
            for (int j = 0; j < 8; j++) {
                int n = wn * 64 + j * 8 + g;
                uint32_t b0 = Bs[(ks + t4) * BST + n];
                uint32_t b1 = Bs[(ks + t4 + 4) * BST + n];
#pragma unroll
                for (int i = 0; i < 2; i++)
                    mma_tf32(acc[i][j][0], acc[i][j][1], acc[i][j][2], acc[i][j][3],
                             af[i][0], af[i][1], af[i][2], af[i][3], b0, b1);
            }
        }
        __syncthreads();
    }

    // Epilogue: add bias, write float2 pairs.
#pragma unroll
    for (int i = 0; i < 2; i++) {
        int r0 = rowBase + wm * 32 + i * 16 + g;
#pragma unroll
        for (int j = 0; j < 8; j++) {
            int c = colBase + wn * 64 + j * 8 + t4 * 2;
            float b0 = bias[c], b1 = bias[c + 1];
            float2 v0 = { acc[i][j][0] + b0, acc[i][j][1] + b1 };
            float2 v1 = { acc[i][j][2] + b0, acc[i][j][3] + b1 };
            *(float2*)(Cm + (size_t)r0 * N + c)       = v0;
            *(float2*)(Cm + (size_t)(r0 + 8) * N + c) = v1;
        }
    }
}

__global__ void __launch_bounds__(256) qkv_gemm_kernel(
    const float* __restrict__ x, const float* __restrict__ W,
    const float* __restrict__ b)
{
    tf32_gemm_body<CC, 3 * CC>(x, W, b, g_qkv);
}

__global__ void __launch_bounds__(256) proj_gemm_kernel(
    const float* __restrict__ W, const float* __restrict__ b,
    float* __restrict__ out)
{
    tf32_gemm_body<CC, CC>(g_y, W, b, out);
}

// ---------------------------------------------------------------------------
// RoPE apply + split qkv into q/k/v with layout [B,H,T,D]. Head-indexed angle.
// ---------------------------------------------------------------------------
__global__ void __launch_bounds__(256) rope_split_kernel() {
    int idx = blockIdx.x * blockDim.x + threadIdx.x;   // < 4194304
    int i = idx & 31;
    int h = (idx >> 5) & (HH - 1);
    int t = (idx >> 9) & (TT - 1);
    int b = idx >> 20;

    float c = g_cos[(h << 5) + i];
    float s = g_sin[(h << 5) + i];

    const float* p = g_qkv + ((size_t)(b * TT + t)) * (3 * CC) + h * DD + 2 * i;
    float2 q = *(const float2*)(p);
    float2 k = *(const float2*)(p + CC);
    float2 v = *(const float2*)(p + 2 * CC);

    float2 qo = { q.x * c - q.y * s, q.y * c + q.x * s };
    float2 ko = { k.x * c - k.y * s, k.y * c + k.x * s };

    size_t o = ((size_t)((b * HH + h) * TT + t)) * DD + 2 * i;
    *(float2*)(g_q + o) = qo;
    *(float2*)(g_k + o) = ko;
    *(float2*)(g_v + o) = v;
}

// ---------------------------------------------------------------------------
// FP32 flash attention, causal (unchanged from passing R2 kernel).
// ---------------------------------------------------------------------------
__global__ void __launch_bounds__(256) flash_kernel() {
    __shared__ float Qs[64][65];
    __shared__ float Ks[32][65];
    __shared__ float Ps[64][33];
    __shared__ float Vs[32][64];

    const int tid = threadIdx.x;
    const int iq = blockIdx.x;
    const int bh = blockIdx.y;
    const int tr = tid >> 4;
    const int tc = tid & 15;

    const float* qp = g_q + ((size_t)bh * TT + iq * 64) * DD;
    const float* kp = g_k + (size_t)bh * TT * DD;
    const float* vp = g_v + (size_t)bh * TT * DD;

#pragma unroll
    for (int it = 0; it < 4; it++) {
        int li = tid + it * 256;
        int r  = li >> 4;
        int d4 = (li & 15) << 2;
        float4 v = *(const float4*)(qp + (size_t)r * DD + d4);
        Qs[r][d4 + 0] = v.x; Qs[r][d4 + 1] = v.y;
        Qs[r][d4 + 2] = v.z; Qs[r][d4 + 3] = v.w;
    }

    float m_i[4], l_i[4], O[4][4];
#pragma unroll
    for (int i = 0; i < 4; i++) {
        m_i[i] = -1e30f; l_i[i] = 0.0f;
#pragma unroll
        for (int j = 0; j < 4; j++) O[i][j] = 0.0f;
    }
    __syncthreads();

    const int nkt = 2 * iq + 2;
    for (int kt = 0; kt < nkt; kt++) {
        const float* kpt = kp + (size_t)kt * 32 * DD;
        const float* vpt = vp + (size_t)kt * 32 * DD;
#pragma unroll
        for (int it = 0; it < 2; it++) {
            int li = tid + it * 256;
            int r  = li >> 4;
            int d4 = (li & 15) << 2;
            float4 kv = *(const float4*)(kpt + (size_t)r * DD + d4);
            Ks[r][d4 + 0] = kv.x; Ks[r][d4 + 1] = kv.y;
            Ks[r][d4 + 2] = kv.z; Ks[r][d4 + 3] = kv.w;
            *(float4*)(&Vs[r][d4]) = *(const float4*)(vpt + (size_t)r * DD + d4);
        }
        __syncthreads();

        float s00 = 0.f, s01 = 0.f, s10 = 0.f, s11 = 0.f;
        float s20 = 0.f, s21 = 0.f, s30 = 0.f, s31 = 0.f;
        const int r0 = tr * 4;
        const int c0 = tc * 2;
#pragma unroll 16
        for (int d = 0; d < 64; d++) {
            float rm0 = Qs[r0 + 0][d];
            float rm1 = Qs[r0 + 1][d];
            float rm2 = Qs[r0 + 2][d];
            float rm3 = Qs[r0 + 3][d];
            float rn0 = Ks[c0 + 0][d];
            float rn1 = Ks[c0 + 1][d];
            s00 += rm0 * rn0; s01 += rm0 * rn1;
            s10 += rm1 * rn0; s11 += rm1 * rn1;
            s20 += rm2 * rn0; s21 += rm2 * rn1;
            s30 += rm3 * rn0; s31 += rm3 * rn1;
        }
        float sarr[4][2] = {{s00, s01}, {s10, s11}, {s20, s21}, {s30, s31}};

        const int qbase = iq * 64 + r0;
        const int kbase = kt * 32 + c0;
#pragma unroll
        for (int i = 0; i < 4; i++) {
#pragma unroll
            for (int jj = 0; jj < 2; jj++) {
                float v = sarr[i][jj] * 0.125f;
                if (kbase + jj > qbase + i) v = -1e30f;
                sarr[i][jj] = v;
            }
        }
#pragma unroll
        for (int i = 0; i < 4; i++) {
            float mx = fmaxf(sarr[i][0], sarr[i][1]);
#pragma unroll
            for (int off = 8; off > 0; off >>= 1)
                mx = fmaxf(mx, __shfl_xor_sync(0xffffffffu, mx, off, 16));
            float mnew  = fmaxf(m_i[i], mx);
            float alpha = __expf(m_i[i] - mnew);
            float p0 = __expf(sarr[i][0] - mnew);
            float p1 = __expf(sarr[i][1] - mnew);
            float rs = p0 + p1;
#pragma unroll
            for (int off = 8; off > 0; off >>= 1)
                rs += __shfl_xor_sync(0xffffffffu, rs, off, 16);
            l_i[i] = l_i[i] * alpha + rs;
            m_i[i] = mnew;
            O[i][0] *= alpha; O[i][1] *= alpha;
            O[i][2] *= alpha; O[i][3] *= alpha;
            Ps[r0 + i][c0 + 0] = p0;
            Ps[r0 + i][c0 + 1] = p1;
        }
        __syncthreads();

        const int dc = tc * 4;
#pragma unroll 8
        for (int kk = 0; kk < 32; kk++) {
            float4 rv = *(const float4*)(&Vs[kk][dc]);
            float p0v = Ps[r0 + 0][kk];
            float p1v = Ps[r0 + 1][kk];
            float p2v = Ps[r0 + 2][kk];
            float p3v = Ps[r0 + 3][kk];
            O[0][0] += p0v * rv.x; O[0][1] += p0v * rv.y; O[0][2] += p0v * rv.z; O[0][3] += p0v * rv.w;
            O[1][0] += p1v * rv.x; O[1][1] += p1v * rv.y; O[1][2] += p1v * rv.z; O[1][3] += p1v * rv.w;
            O[2][0] += p2v * rv.x; O[2][1] += p2v * rv.y; O[2][2] += p2v * rv.z; O[2][3] += p2v * rv.w;
            O[3][0] += p3v * rv.x; O[3][1] += p3v * rv.y; O[3][2] += p3v * rv.z; O[3][3] += p3v * rv.w;
        }
        __syncthreads();
    }

    const int b = bh >> 4;
    const int h = bh & 15;
#pragma unroll
    for (int i = 0; i < 4; i++) {
        int qrow = iq * 64 + tr * 4 + i;
        float inv = 1.0f / l_i[i];
        float4 o;
        o.x = O[i][0] * inv; o.y = O[i][1] * inv;
        o.z = O[i][2] * inv; o.w = O[i][3] * inv;
        *(float4*)(g_y + ((size_t)(b * TT + qrow)) * CC + h * DD + tc * 4) = o;
    }
}

// ---------------------------------------------------------------------------
// Launch
// ---------------------------------------------------------------------------
extern "C" void kernel_launch(void* const* d_in, const int* in_sizes, int n_in,
                              void* d_out, int out_size) {
    const float* x      = (const float*)d_in[0];
    const float* W_attn = (const float*)d_in[1];
    const float* b_attn = (const float*)d_in[2];
    const float* W_proj = (const float*)d_in[3];
    const float* b_proj = (const float*)d_in[4];
    float* out = (float*)d_out;

    rope_cache_kernel<<<2, 256>>>();

    // QKV projection: [8192,1024] @ [1024,3072] + bias (tf32 tensor cores)
    qkv_gemm_kernel<<<dim3((3 * CC) / 128, BT / 128), 256>>>(x, W_attn, b_attn);

    // RoPE + split into q/k/v [B,H,T,D]
    rope_split_kernel<<<(BB * TT * HH * 32) / 256, 256>>>();

    // Causal flash attention (fp32)
    flash_kernel<<<dim3(TT / 64, BB * HH), 256>>>();

    // Output projection: [8192,1024] @ [1024,1024] + bias (tf32 tensor cores)
    proj_gemm_kernel<<<dim3(CC / 128, BT / 128), 256>>>(W_proj, b_proj, out);
}

// round 4
// speedup vs baseline: 3.0114x; 1.8789x over previous
#include <cuda_runtime.h>
#include <math.h>
#include <stdint.h>

// Problem constants
#define BB 4
#define TT 2048
#define CC 1024
#define HH 16
#define DD 64
#define BT (BB*TT)          // 8192 rows

// ---------------------------------------------------------------------------
// Scratch
// ---------------------------------------------------------------------------
__device__ float g_qkv[(size_t)BT * 3 * CC];
__device__ float g_q[(size_t)BB * HH * TT * DD];
__device__ float g_k[(size_t)BB * HH * TT * DD];
__device__ float g_v[(size_t)BB * HH * TT * DD];
__device__ float g_y[(size_t)BT * CC];
__device__ float g_cos[HH * 32];                    // indexed by HEAD (reference quirk)
__device__ float g_sin[HH * 32];

// ---------------------------------------------------------------------------
// RoPE cache (head-indexed angle, reference quirk)
// ---------------------------------------------------------------------------
__global__ void __launch_bounds__(256) rope_cache_kernel() {
    int idx = blockIdx.x * blockDim.x + threadIdx.x;
    if (idx >= HH * 32) return;
    int h = idx >> 5;
    int i = idx & 31;
    float theta = (float)pow(10000.0, -((double)(2 * i)) / 64.0);
    float ang = (float)h * theta;
    double sv, cv;
    sincos((double)ang, &sv, &cv);
    g_cos[idx] = (float)cv;
    g_sin[idx] = (float)sv;
}

// ---------------------------------------------------------------------------
// TF32 mma helpers
// ---------------------------------------------------------------------------
__device__ __forceinline__ uint32_t f2tf32(float x) {
    uint32_t r;
    asm("cvt.rna.tf32.f32 %0, %1;" : "=r"(r) : "f"(x));
    return r;
}

__device__ __forceinline__ void mma_tf32(
    float& d0, float& d1, float& d2, float& d3,
    uint32_t a0, uint32_t a1, uint32_t a2, uint32_t a3,
    uint32_t b0, uint32_t b1)
{
    asm volatile(
        "mma.sync.aligned.m16n8k8.row.col.f32.tf32.tf32.f32 "
        "{%0,%1,%2,%3}, {%4,%5,%6,%7}, {%8,%9}, {%0,%1,%2,%3};"
        : "+f"(d0), "+f"(d1), "+f"(d2), "+f"(d3)
        : "r"(a0), "r"(a1), "r"(a2), "r"(a3), "r"(b0), "r"(b1));
}

// ---------------------------------------------------------------------------
// TF32 GEMM (unchanged from R3): C[M,N] = A @ B + bias
// ---------------------------------------------------------------------------
template<int K, int N>
__device__ __forceinline__ void tf32_gemm_body(
    const float* __restrict__ A, const float* __restrict__ Bm,
    const float* __restrict__ bias, float* __restrict__ Cm)
{
    constexpr int BM = 128, BN = 128, BK = 32;
    constexpr int AST = BK + 4;
    constexpr int BST = BN + 8;
    __shared__ uint32_t As[BM * AST];
    __shared__ uint32_t Bs[BK * BST];

    const int tid  = threadIdx.x;
    const int lane = tid & 31;
    const int warp = tid >> 5;
    const int wm = warp >> 1;
    const int wn = warp & 1;
    const int g  = lane >> 2;
    const int t4 = lane & 3;
    const int rowBase = blockIdx.y * BM;
    const int colBase = blockIdx.x * BN;

    const float* Ap = A + (size_t)rowBase * K;
    const float* Bp = Bm + colBase;

    float acc[2][8][4];
#pragma unroll
    for (int i = 0; i < 2; i++)
#pragma unroll
        for (int j = 0; j < 8; j++)
#pragma unroll
            for (int q = 0; q < 4; q++) acc[i][j][q] = 0.0f;

    for (int k0 = 0; k0 < K; k0 += BK) {
#pragma unroll
        for (int it = 0; it < 4; it++) {
            int li = tid + it * 256;
            int r  = li >> 3;
            int kk = (li & 7) << 2;
            float4 v = *(const float4*)(Ap + (size_t)r * K + k0 + kk);
            uint32_t* dst = &As[r * AST + kk];
            dst[0] = f2tf32(v.x); dst[1] = f2tf32(v.y);
            dst[2] = f2tf32(v.z); dst[3] = f2tf32(v.w);
        }
#pragma unroll
        for (int it = 0; it < 4; it++) {
            int li = tid + it * 256;
            int r  = li >> 5;
            int c  = (li & 31) << 2;
            float4 v = *(const float4*)(Bp + (size_t)(k0 + r) * N + c);
            uint32_t* dst = &Bs[r * BST + c];
            dst[0] = f2tf32(v.x); dst[1] = f2tf32(v.y);
            dst[2] = f2tf32(v.z); dst[3] = f2tf32(v.w);
        }
        __syncthreads();

#pragma unroll
        for (int ks = 0; ks < BK; ks += 8) {
            uint32_t af[2][4];
#pragma unroll
            for (int i = 0; i < 2; i++) {
                int m = wm * 32 + i * 16 + g;
                af[i][0] = As[m * AST + ks + t4];
                af[i][1] = As[(m + 8) * AST + ks + t4];
                af[i][2] = As[m * AST + ks + t4 + 4];
                af[i][3] = As[(m + 8) * AST + ks + t4 + 4];
            }
#pragma unroll
            for (int j = 0; j < 8; j++) {
                int n = wn * 64 + j * 8 + g;
                uint32_t b0 = Bs[(ks + t4) * BST + n];
                uint32_t b1 = Bs[(ks + t4 + 4) * BST + n];
#pragma unroll
                for (int i = 0; i < 2; i++)
                    mma_tf32(acc[i][j][0], acc[i][j][1], acc[i][j][2], acc[i][j][3],
                             af[i][0], af[i][1], af[i][2], af[i][3], b0, b1);
            }
        }
        __syncthreads();
    }

#pragma unroll
    for (int i = 0; i < 2; i++) {
        int r0 = rowBase + wm * 32 + i * 16 + g;
#pragma unroll
        for (int j = 0; j < 8; j++) {
            int c = colBase + wn * 64 + j * 8 + t4 * 2;
            float b0 = bias[c], b1 = bias[c + 1];
            float2 v0 = { acc[i][j][0] + b0, acc[i][j][1] + b1 };
            float2 v1 = { acc[i][j][2] + b0, acc[i][j][3] + b1 };
            *(float2*)(Cm + (size_t)r0 * N + c)       = v0;
            *(float2*)(Cm + (size_t)(r0 + 8) * N + c) = v1;
        }
    }
}

__global__ void __launch_bounds__(256) qkv_gemm_kernel(
    const float* __restrict__ x, const float* __restrict__ W,
    const float* __restrict__ b)
{
    tf32_gemm_body<CC, 3 * CC>(x, W, b, g_qkv);
}

__global__ void __launch_bounds__(256) proj_gemm_kernel(
    const float* __restrict__ W, const float* __restrict__ b,
    float* __restrict__ out)
{
    tf32_gemm_body<CC, CC>(g_y, W, b, out);
}

// ---------------------------------------------------------------------------
// RoPE apply + split (unchanged)
// ---------------------------------------------------------------------------
__global__ void __launch_bounds__(256) rope_split_kernel() {
    int idx = blockIdx.x * blockDim.x + threadIdx.x;
    int i = idx & 31;
    int h = (idx >> 5) & (HH - 1);
    int t = (idx >> 9) & (TT - 1);
    int b = idx >> 20;

    float c = g_cos[(h << 5) + i];
    float s = g_sin[(h << 5) + i];

    const float* p = g_qkv + ((size_t)(b * TT + t)) * (3 * CC) + h * DD + 2 * i;
    float2 q = *(const float2*)(p);
    float2 k = *(const float2*)(p + CC);
    float2 v = *(const float2*)(p + 2 * CC);

    float2 qo = { q.x * c - q.y * s, q.y * c + q.x * s };
    float2 ko = { k.x * c - k.y * s, k.y * c + k.x * s };

    size_t o = ((size_t)((b * HH + h) * TT + t)) * DD + 2 * i;
    *(float2*)(g_q + o) = qo;
    *(float2*)(g_k + o) = ko;
    *(float2*)(g_v + o) = v;
}

// ---------------------------------------------------------------------------
// TF32 tensor-core flash attention, causal.
// Block = 128 threads (4 warps); grid = (T/64, B*H).
// Warp w owns q-rows [iq*64 + w*16, +16) across the FULL 64-wide key tile,
// so the online softmax is warp-local (quad shuffles only).
// Q fragments register-resident (scale folded). K/V tiles in smem as tf32,
// stride 68 (conflict-free for both S and PV B-fragment access patterns).
// P operand for PV built from S accumulators via quad shuffles (no P smem).
// ---------------------------------------------------------------------------
__global__ void __launch_bounds__(128) flash_kernel() {
    constexpr int STR = 68;
    __shared__ uint32_t Ks[64 * STR];
    __shared__ uint32_t Vs[64 * STR];

    const int tid  = threadIdx.x;
    const int lane = tid & 31;
    const int warp = tid >> 5;
    const int g    = lane >> 2;     // 0..7
    const int t4   = lane & 3;      // 0..3
    const int iq   = blockIdx.x;    // 0..31
    const int bh   = blockIdx.y;    // 0..63

    const int qrow_g = iq * 64 + warp * 16 + g;   // this thread's first q row
    const float* qp = g_q + ((size_t)bh * TT + iq * 64 + warp * 16) * DD;
    const float* kp = g_k + (size_t)bh * TT * DD;
    const float* vp = g_v + (size_t)bh * TT * DD;

    // Q fragments, register-resident, softmax scale 1/8 folded in.
    uint32_t qf[8][4];
#pragma unroll
    for (int ks = 0; ks < 8; ks++) {
        int c = ks * 8 + t4;
        qf[ks][0] = f2tf32(0.125f * qp[(size_t)g * DD + c]);
        qf[ks][1] = f2tf32(0.125f * qp[(size_t)(g + 8) * DD + c]);
        qf[ks][2] = f2tf32(0.125f * qp[(size_t)g * DD + c + 4]);
        qf[ks][3] = f2tf32(0.125f * qp[(size_t)(g + 8) * DD + c + 4]);
    }

    float oacc[8][4];
#pragma unroll
    for (int j = 0; j < 8; j++)
#pragma unroll
        for (int q = 0; q < 4; q++) oacc[j][q] = 0.0f;
    float m_g = -1e30f, m_h = -1e30f, l_g = 0.0f, l_h = 0.0f;

    const int nkt = iq + 1;     // key tiles of 64
    for (int kt = 0; kt < nkt; kt++) {
        // ---- load K/V tiles (64x64) as tf32 ----
        const float* kpt = kp + (size_t)kt * 64 * DD;
        const float* vpt = vp + (size_t)kt * 64 * DD;
#pragma unroll
        for (int it = 0; it < 8; it++) {
            int slot = tid + it * 128;       // 0..1023
            int r = slot >> 4;
            int c = (slot & 15) << 2;
            float4 kv = *(const float4*)(kpt + (size_t)r * DD + c);
            uint32_t* dk = &Ks[r * STR + c];
            dk[0] = f2tf32(kv.x); dk[1] = f2tf32(kv.y);
            dk[2] = f2tf32(kv.z); dk[3] = f2tf32(kv.w);
            float4 vv = *(const float4*)(vpt + (size_t)r * DD + c);
            uint32_t* dv = &Vs[r * STR + c];
            dv[0] = f2tf32(vv.x); dv[1] = f2tf32(vv.y);
            dv[2] = f2tf32(vv.z); dv[3] = f2tf32(vv.w);
        }
        __syncthreads();

        // ---- S = (Q/8) @ K^T : warp computes 16x64 ----
        float sacc[8][4];
#pragma unroll
        for (int j = 0; j < 8; j++) {
            sacc[j][0] = 0.f; sacc[j][1] = 0.f; sacc[j][2] = 0.f; sacc[j][3] = 0.f;
            const uint32_t* kb = &Ks[(j * 8 + g) * STR];
#pragma unroll
            for (int ks = 0; ks < 8; ks++) {
                uint32_t b0 = kb[ks * 8 + t4];
                uint32_t b1 = kb[ks * 8 + t4 + 4];
                mma_tf32(sacc[j][0], sacc[j][1], sacc[j][2], sacc[j][3],
                         qf[ks][0], qf[ks][1], qf[ks][2], qf[ks][3], b0, b1);
            }
        }

        // ---- causal mask (only the diagonal tile needs it) ----
        if (kt == iq) {
#pragma unroll
            for (int j = 0; j < 8; j++) {
                int col = kt * 64 + j * 8 + t4 * 2;
                if (col     > qrow_g)     sacc[j][0] = -1e30f;
                if (col + 1 > qrow_g)     sacc[j][1] = -1e30f;
                if (col     > qrow_g + 8) sacc[j][2] = -1e30f;
                if (col + 1 > qrow_g + 8) sacc[j][3] = -1e30f;
            }
        }

        // ---- online softmax (rows g and g+8; quad-local reductions) ----
        float rm_g = -1e30f, rm_h = -1e30f;
#pragma unroll
        for (int j = 0; j < 8; j++) {
            rm_g = fmaxf(rm_g, fmaxf(sacc[j][0], sacc[j][1]));
            rm_h = fmaxf(rm_h, fmaxf(sacc[j][2], sacc[j][3]));
        }
        rm_g = fmaxf(rm_g, __shfl_xor_sync(0xffffffffu, rm_g, 1));
        rm_g = fmaxf(rm_g, __shfl_xor_sync(0xffffffffu, rm_g, 2));
        rm_h = fmaxf(rm_h, __shfl_xor_sync(0xffffffffu, rm_h, 1));
        rm_h = fmaxf(rm_h, __shfl_xor_sync(0xffffffffu, rm_h, 2));

        float mn_g = fmaxf(m_g, rm_g);
        float mn_h = fmaxf(m_h, rm_h);
        float al_g = __expf(m_g - mn_g);
        float al_h = __expf(m_h - mn_h);
        m_g = mn_g; m_h = mn_h;

        float sum_g = 0.0f, sum_h = 0.0f;
        uint32_t pf[8][4];
#pragma unroll
        for (int j = 0; j < 8; j++) {
            float p0 = __expf(sacc[j][0] - mn_g);
            float p1 = __expf(sacc[j][1] - mn_g);
            float p2 = __expf(sacc[j][2] - mn_h);
            float p3 = __expf(sacc[j][3] - mn_h);
            sum_g += p0 + p1;
            sum_h += p2 + p3;
            pf[j][0] = f2tf32(p0); pf[j][1] = f2tf32(p1);
            pf[j][2] = f2tf32(p2); pf[j][3] = f2tf32(p3);
        }
        sum_g += __shfl_xor_sync(0xffffffffu, sum_g, 1);
        sum_g += __shfl_xor_sync(0xffffffffu, sum_g, 2);
        sum_h += __shfl_xor_sync(0xffffffffu, sum_h, 1);
        sum_h += __shfl_xor_sync(0xffffffffu, sum_h, 2);
        l_g = l_g * al_g + sum_g;
        l_h = l_h * al_h + sum_h;

#pragma unroll
        for (int j = 0; j < 8; j++) {
            oacc[j][0] *= al_g; oacc[j][1] *= al_g;
            oacc[j][2] *= al_h; oacc[j][3] *= al_h;
        }

        // ---- O += P @ V ----
        const int srcA = (lane & ~3) | (t4 >> 1);   // quad lane holding col t4
        const int srcB = srcA + 2;                  // quad lane holding col t4+4
        const bool odd = (t4 & 1);
#pragma unroll
        for (int ks = 0; ks < 8; ks++) {
            // Build A-fragment of P for k-step ks from accumulator-layout pf[ks].
            uint32_t x0 = __shfl_sync(0xffffffffu, pf[ks][0], srcA);
            uint32_t x1 = __shfl_sync(0xffffffffu, pf[ks][1], srcA);
            uint32_t a0 = odd ? x1 : x0;                       // row g,   col t4
            uint32_t x2 = __shfl_sync(0xffffffffu, pf[ks][2], srcA);
            uint32_t x3 = __shfl_sync(0xffffffffu, pf[ks][3], srcA);
            uint32_t a1 = odd ? x3 : x2;                       // row g+8, col t4
            uint32_t y0 = __shfl_sync(0xffffffffu, pf[ks][0], srcB);
            uint32_t y1 = __shfl_sync(0xffffffffu, pf[ks][1], srcB);
            uint32_t a2 = odd ? y1 : y0;                       // row g,   col t4+4
            uint32_t y2 = __shfl_sync(0xffffffffu, pf[ks][2], srcB);
            uint32_t y3 = __shfl_sync(0xffffffffu, pf[ks][3], srcB);
            uint32_t a3 = odd ? y3 : y2;                       // row g+8, col t4+4

            const uint32_t* vb0 = &Vs[(ks * 8 + t4) * STR];
            const uint32_t* vb1 = &Vs[(ks * 8 + t4 + 4) * STR];
#pragma unroll
            for (int j = 0; j < 8; j++) {
                uint32_t b0 = vb0[j * 8 + g];
                uint32_t b1 = vb1[j * 8 + g];
                mma_tf32(oacc[j][0], oacc[j][1], oacc[j][2], oacc[j][3],
                         a0, a1, a2, a3, b0, b1);
            }
        }
        __syncthreads();
    }

    // ---- epilogue: normalize, write y[B,T,C] ----
    const int b = bh >> 4;
    const int h = bh & 15;
    const float inv_g = 1.0f / l_g;
    const float inv_h = 1.0f / l_h;
#pragma unroll
    for (int j = 0; j < 8; j++) {
        int c = h * DD + j * 8 + t4 * 2;
        float2 v0 = { oacc[j][0] * inv_g, oacc[j][1] * inv_g };
        float2 v1 = { oacc[j][2] * inv_h, oacc[j][3] * inv_h };
        *(float2*)(g_y + (size_t)(b * TT + qrow_g) * CC + c)       = v0;
        *(float2*)(g_y + (size_t)(b * TT + qrow_g + 8) * CC + c)   = v1;
    }
}

// ---------------------------------------------------------------------------
// Launch
// ---------------------------------------------------------------------------
extern "C" void kernel_launch(void* const* d_in, const int* in_sizes, int n_in,
                              void* d_out, int out_size) {
    const float* x      = (const float*)d_in[0];
    const float* W_attn = (const float*)d_in[1];
    const float* b_attn = (const float*)d_in[2];
    const float* W_proj = (const float*)d_in[3];
    const float* b_proj = (const float*)d_in[4];
    float* out = (float*)d_out;

    rope_cache_kernel<<<2, 256>>>();

    qkv_gemm_kernel<<<dim3((3 * CC) / 128, BT / 128), 256>>>(x, W_attn, b_attn);

    rope_split_kernel<<<(BB * TT * HH * 32) / 256, 256>>>();

    flash_kernel<<<dim3(TT / 64, BB * HH), 128>>>();

    proj_gemm_kernel<<<dim3(CC / 128, BT / 128), 256>>>(W_proj, b_proj, out);
}

// round 5
// speedup vs baseline: 3.3917x; 1.1263x over previous
#include <cuda_runtime.h>
#include <math.h>
#include <stdint.h>

// Problem constants
#define BB 4
#define TT 2048
#define CC 1024
#define HH 16
#define DD 64
#define BT (BB*TT)          // 8192 rows

// ---------------------------------------------------------------------------
// Scratch
// ---------------------------------------------------------------------------
__device__ float g_qkv[(size_t)BT * 3 * CC];
__device__ float g_q[(size_t)BB * HH * TT * DD];
__device__ float g_k[(size_t)BB * HH * TT * DD];
__device__ float g_v[(size_t)BB * HH * TT * DD];
__device__ float g_y[(size_t)BT * CC];
__device__ float g_cos[HH * 32];                    // indexed by HEAD (reference quirk)
__device__ float g_sin[HH * 32];

// ---------------------------------------------------------------------------
// RoPE cache (head-indexed angle, reference quirk)
// ---------------------------------------------------------------------------
__global__ void __launch_bounds__(256) rope_cache_kernel() {
    int idx = blockIdx.x * blockDim.x + threadIdx.x;
    if (idx >= HH * 32) return;
    int h = idx >> 5;
    int i = idx & 31;
    float theta = (float)pow(10000.0, -((double)(2 * i)) / 64.0);
    float ang = (float)h * theta;
    double sv, cv;
    sincos((double)ang, &sv, &cv);
    g_cos[idx] = (float)cv;
    g_sin[idx] = (float)sv;
}

// ---------------------------------------------------------------------------
// TF32 mma helpers
// ---------------------------------------------------------------------------
__device__ __forceinline__ uint32_t f2tf32(float x) {
    uint32_t r;
    asm("cvt.rna.tf32.f32 %0, %1;" : "=r"(r) : "f"(x));
    return r;
}

__device__ __forceinline__ void mma_tf32(
    float& d0, float& d1, float& d2, float& d3,
    uint32_t a0, uint32_t a1, uint32_t a2, uint32_t a3,
    uint32_t b0, uint32_t b1)
{
    asm volatile(
        "mma.sync.aligned.m16n8k8.row.col.f32.tf32.tf32.f32 "
        "{%0,%1,%2,%3}, {%4,%5,%6,%7}, {%8,%9}, {%0,%1,%2,%3};"
        : "+f"(d0), "+f"(d1), "+f"(d2), "+f"(d3)
        : "r"(a0), "r"(a1), "r"(a2), "r"(a3), "r"(b0), "r"(b1));
}

// ---------------------------------------------------------------------------
// TF32 GEMM (unchanged from R3): C[M,N] = A @ B + bias
// ---------------------------------------------------------------------------
template<int K, int N>
__device__ __forceinline__ void tf32_gemm_body(
    const float* __restrict__ A, const float* __restrict__ Bm,
    const float* __restrict__ bias, float* __restrict__ Cm)
{
    constexpr int BM = 128, BN = 128, BK = 32;
    constexpr int AST = BK + 4;
    constexpr int BST = BN + 8;
    __shared__ uint32_t As[BM * AST];
    __shared__ uint32_t Bs[BK * BST];

    const int tid  = threadIdx.x;
    const int lane = tid & 31;
    const int warp = tid >> 5;
    const int wm = warp >> 1;
    const int wn = warp & 1;
    const int g  = lane >> 2;
    const int t4 = lane & 3;
    const int rowBase = blockIdx.y * BM;
    const int colBase = blockIdx.x * BN;

    const float* Ap = A + (size_t)rowBase * K;
    const float* Bp = Bm + colBase;

    float acc[2][8][4];
#pragma unroll
    for (int i = 0; i < 2; i++)
#pragma unroll
        for (int j = 0; j < 8; j++)
#pragma unroll
            for (int q = 0; q < 4; q++) acc[i][j][q] = 0.0f;

    for (int k0 = 0; k0 < K; k0 += BK) {
#pragma unroll
        for (int it = 0; it < 4; it++) {
            int li = tid + it * 256;
            int r  = li >> 3;
            int kk = (li & 7) << 2;
            float4 v = *(const float4*)(Ap + (size_t)r * K + k0 + kk);
            uint32_t* dst = &As[r * AST + kk];
            dst[0] = f2tf32(v.x); dst[1] = f2tf32(v.y);
            dst[2] = f2tf32(v.z); dst[3] = f2tf32(v.w);
        }
#pragma unroll
        for (int it = 0; it < 4; it++) {
            int li = tid + it * 256;
            int r  = li >> 5;
            int c  = (li & 31) << 2;
            float4 v = *(const float4*)(Bp + (size_t)(k0 + r) * N + c);
            uint32_t* dst = &Bs[r * BST + c];
            dst[0] = f2tf32(v.x); dst[1] = f2tf32(v.y);
            dst[2] = f2tf32(v.z); dst[3] = f2tf32(v.w);
        }
        __syncthreads();

#pragma unroll
        for (int ks = 0; ks < BK; ks += 8) {
            uint32_t af[2][4];
#pragma unroll
            for (int i = 0; i < 2; i++) {
                int m = wm * 32 + i * 16 + g;
                af[i][0] = As[m * AST + ks + t4];
                af[i][1] = As[(m + 8) * AST + ks + t4];
                af[i][2] = As[m * AST + ks + t4 + 4];
                af[i][3] = As[(m + 8) * AST + ks + t4 + 4];
            }
#pragma unroll
            for (int j = 0; j < 8; j++) {
                int n = wn * 64 + j * 8 + g;
                uint32_t b0 = Bs[(ks + t4) * BST + n];
                uint32_t b1 = Bs[(ks + t4 + 4) * BST + n];
#pragma unroll
                for (int i = 0; i < 2; i++)
                    mma_tf32(acc[i][j][0], acc[i][j][1], acc[i][j][2], acc[i][j][3],
                             af[i][0], af[i][1], af[i][2], af[i][3], b0, b1);
            }
        }
        __syncthreads();
    }

#pragma unroll
    for (int i = 0; i < 2; i++) {
        int r0 = rowBase + wm * 32 + i * 16 + g;
#pragma unroll
        for (int j = 0; j < 8; j++) {
            int c = colBase + wn * 64 + j * 8 + t4 * 2;
            float b0 = bias[c], b1 = bias[c + 1];
            float2 v0 = { acc[i][j][0] + b0, acc[i][j][1] + b1 };
            float2 v1 = { acc[i][j][2] + b0, acc[i][j][3] + b1 };
            *(float2*)(Cm + (size_t)r0 * N + c)       = v0;
            *(float2*)(Cm + (size_t)(r0 + 8) * N + c) = v1;
        }
    }
}

__global__ void __launch_bounds__(256) qkv_gemm_kernel(
    const float* __restrict__ x, const float* __restrict__ W,
    const float* __restrict__ b)
{
    tf32_gemm_body<CC, 3 * CC>(x, W, b, g_qkv);
}

__global__ void __launch_bounds__(256) proj_gemm_kernel(
    const float* __restrict__ W, const float* __restrict__ b,
    float* __restrict__ out)
{
    tf32_gemm_body<CC, CC>(g_y, W, b, out);
}

// ---------------------------------------------------------------------------
// RoPE apply + split (unchanged)
// ---------------------------------------------------------------------------
__global__ void __launch_bounds__(256) rope_split_kernel() {
    int idx = blockIdx.x * blockDim.x + threadIdx.x;
    int i = idx & 31;
    int h = (idx >> 5) & (HH - 1);
    int t = (idx >> 9) & (TT - 1);
    int b = idx >> 20;

    float c = g_cos[(h << 5) + i];
    float s = g_sin[(h << 5) + i];

    const float* p = g_qkv + ((size_t)(b * TT + t)) * (3 * CC) + h * DD + 2 * i;
    float2 q = *(const float2*)(p);
    float2 k = *(const float2*)(p + CC);
    float2 v = *(const float2*)(p + 2 * CC);

    float2 qo = { q.x * c - q.y * s, q.y * c + q.x * s };
    float2 ko = { k.x * c - k.y * s, k.y * c + k.x * s };

    size_t o = ((size_t)((b * HH + h) * TT + t)) * DD + 2 * i;
    *(float2*)(g_q + o) = qo;
    *(float2*)(g_k + o) = ko;
    *(float2*)(g_v + o) = v;
}

// ---------------------------------------------------------------------------
// TF32 tensor-core flash attention, causal.
// R5 changes vs R4:
//  - V stored with within-8 row permutation sigma^{-1}: row r -> slot
//    (r>>1)|((r&1)<<2). This makes the S/P accumulator register layout directly
//    usable as the PV mma A-operand (order pf0,pf2,pf1,pf3): zero shuffles.
//  - V smem stride 72 (8 mod 32): PV B-fragment banks 8*t4+g, bijective ->
//    conflict-free (was 68 -> 2-3 way conflicts).
//  - Tile conversion stores packed as STS.128 (uint4), 4x fewer store instrs.
// ---------------------------------------------------------------------------
__global__ void __launch_bounds__(128) flash_kernel() {
    constexpr int KSTR = 68;    // 4 mod 32: S B-frag banks 4g+t4 (bijective)
    constexpr int VSTR = 72;    // 8 mod 32: PV B-frag banks 8t4+g (bijective)
    __shared__ uint32_t Ks[64 * KSTR];
    __shared__ uint32_t Vs[64 * VSTR];

    const int tid  = threadIdx.x;
    const int lane = tid & 31;
    const int warp = tid >> 5;
    const int g    = lane >> 2;     // 0..7
    const int t4   = lane & 3;      // 0..3
    const int iq   = blockIdx.x;    // 0..31
    const int bh   = blockIdx.y;    // 0..63

    const int qrow_g = iq * 64 + warp * 16 + g;
    const float* qp = g_q + ((size_t)bh * TT + iq * 64 + warp * 16) * DD;
    const float* kp = g_k + (size_t)bh * TT * DD;
    const float* vp = g_v + (size_t)bh * TT * DD;

    // Q fragments, register-resident, softmax scale 1/8 folded in.
    uint32_t qf[8][4];
#pragma unroll
    for (int ks = 0; ks < 8; ks++) {
        int c = ks * 8 + t4;
        qf[ks][0] = f2tf32(0.125f * qp[(size_t)g * DD + c]);
        qf[ks][1] = f2tf32(0.125f * qp[(size_t)(g + 8) * DD + c]);
        qf[ks][2] = f2tf32(0.125f * qp[(size_t)g * DD + c + 4]);
        qf[ks][3] = f2tf32(0.125f * qp[(size_t)(g + 8) * DD + c + 4]);
    }

    float oacc[8][4];
#pragma unroll
    for (int j = 0; j < 8; j++)
#pragma unroll
        for (int q = 0; q < 4; q++) oacc[j][q] = 0.0f;
    float m_g = -1e30f, m_h = -1e30f, l_g = 0.0f, l_h = 0.0f;

    const int nkt = iq + 1;     // key tiles of 64
    for (int kt = 0; kt < nkt; kt++) {
        // ---- load K/V tiles (64x64) as tf32, packed STS.128 ----
        const float* kpt = kp + (size_t)kt * 64 * DD;
        const float* vpt = vp + (size_t)kt * 64 * DD;
#pragma unroll
        for (int it = 0; it < 8; it++) {
            int slot = tid + it * 128;       // 0..1023
            int r = slot >> 4;
            int c = (slot & 15) << 2;
            float4 kv = *(const float4*)(kpt + (size_t)r * DD + c);
            uint4 pk;
            pk.x = f2tf32(kv.x); pk.y = f2tf32(kv.y);
            pk.z = f2tf32(kv.z); pk.w = f2tf32(kv.w);
            *(uint4*)(&Ks[r * KSTR + c]) = pk;
            // V: permute row within its 8-row chunk: r -> (r>>1)|((r&1)<<2)
            int pr = (r & 0x38) | (((r & 7) >> 1) | ((r & 1) << 2));
            float4 vv = *(const float4*)(vpt + (size_t)r * DD + c);
            uint4 pv;
            pv.x = f2tf32(vv.x); pv.y = f2tf32(vv.y);
            pv.z = f2tf32(vv.z); pv.w = f2tf32(vv.w);
            *(uint4*)(&Vs[pr * VSTR + c]) = pv;
        }
        __syncthreads();

        // ---- S = (Q/8) @ K^T : warp computes 16x64 ----
        float sacc[8][4];
#pragma unroll
        for (int j = 0; j < 8; j++) {
            sacc[j][0] = 0.f; sacc[j][1] = 0.f; sacc[j][2] = 0.f; sacc[j][3] = 0.f;
            const uint32_t* kb = &Ks[(j * 8 + g) * KSTR];
#pragma unroll
            for (int ks = 0; ks < 8; ks++) {
                uint32_t b0 = kb[ks * 8 + t4];
                uint32_t b1 = kb[ks * 8 + t4 + 4];
                mma_tf32(sacc[j][0], sacc[j][1], sacc[j][2], sacc[j][3],
                         qf[ks][0], qf[ks][1], qf[ks][2], qf[ks][3], b0, b1);
            }
        }

        // ---- causal mask (only the diagonal tile) ----
        if (kt == iq) {
#pragma unroll
            for (int j = 0; j < 8; j++) {
                int col = kt * 64 + j * 8 + t4 * 2;
                if (col     > qrow_g)     sacc[j][0] = -1e30f;
                if (col + 1 > qrow_g)     sacc[j][1] = -1e30f;
                if (col     > qrow_g + 8) sacc[j][2] = -1e30f;
                if (col + 1 > qrow_g + 8) sacc[j][3] = -1e30f;
            }
        }

        // ---- online softmax (rows g and g+8; quad reductions) ----
        float rm_g = -1e30f, rm_h = -1e30f;
#pragma unroll
        for (int j = 0; j < 8; j++) {
            rm_g = fmaxf(rm_g, fmaxf(sacc[j][0], sacc[j][1]));
            rm_h = fmaxf(rm_h, fmaxf(sacc[j][2], sacc[j][3]));
        }
        rm_g = fmaxf(rm_g, __shfl_xor_sync(0xffffffffu, rm_g, 1));
        rm_g = fmaxf(rm_g, __shfl_xor_sync(0xffffffffu, rm_g, 2));
        rm_h = fmaxf(rm_h, __shfl_xor_sync(0xffffffffu, rm_h, 1));
        rm_h = fmaxf(rm_h, __shfl_xor_sync(0xffffffffu, rm_h, 2));

        float mn_g = fmaxf(m_g, rm_g);
        float mn_h = fmaxf(m_h, rm_h);
        float al_g = __expf(m_g - mn_g);
        float al_h = __expf(m_h - mn_h);
        m_g = mn_g; m_h = mn_h;

        float sum_g = 0.0f, sum_h = 0.0f;
        uint32_t pf[8][4];
#pragma unroll
        for (int j = 0; j < 8; j++) {
            float p0 = __expf(sacc[j][0] - mn_g);
            float p1 = __expf(sacc[j][1] - mn_g);
            float p2 = __expf(sacc[j][2] - mn_h);
            float p3 = __expf(sacc[j][3] - mn_h);
            sum_g += p0 + p1;
            sum_h += p2 + p3;
            pf[j][0] = f2tf32(p0); pf[j][1] = f2tf32(p1);
            pf[j][2] = f2tf32(p2); pf[j][3] = f2tf32(p3);
        }
        sum_g += __shfl_xor_sync(0xffffffffu, sum_g, 1);
        sum_g += __shfl_xor_sync(0xffffffffu, sum_g, 2);
        sum_h += __shfl_xor_sync(0xffffffffu, sum_h, 1);
        sum_h += __shfl_xor_sync(0xffffffffu, sum_h, 2);
        l_g = l_g * al_g + sum_g;
        l_h = l_h * al_h + sum_h;

#pragma unroll
        for (int j = 0; j < 8; j++) {
            oacc[j][0] *= al_g; oacc[j][1] *= al_g;
            oacc[j][2] *= al_h; oacc[j][3] *= al_h;
        }

        // ---- O += P @ V : accumulator regs feed mma A directly (V rows
        //      pre-permuted in smem), no shuffles ----
#pragma unroll
        for (int ks = 0; ks < 8; ks++) {
            const uint32_t* vb0 = &Vs[(ks * 8 + t4) * VSTR];
            const uint32_t* vb1 = &Vs[(ks * 8 + t4 + 4) * VSTR];
#pragma unroll
            for (int j = 0; j < 8; j++) {
                uint32_t b0 = vb0[j * 8 + g];
                uint32_t b1 = vb1[j * 8 + g];
                mma_tf32(oacc[j][0], oacc[j][1], oacc[j][2], oacc[j][3],
                         pf[ks][0], pf[ks][2], pf[ks][1], pf[ks][3], b0, b1);
            }
        }
        __syncthreads();
    }

    // ---- epilogue: normalize, write y[B,T,C] ----
    const int b = bh >> 4;
    const int h = bh & 15;
    const float inv_g = 1.0f / l_g;
    const float inv_h = 1.0f / l_h;
#pragma unroll
    for (int j = 0; j < 8; j++) {
        int c = h * DD + j * 8 + t4 * 2;
        float2 v0 = { oacc[j][0] * inv_g, oacc[j][1] * inv_g };
        float2 v1 = { oacc[j][2] * inv_h, oacc[j][3] * inv_h };
        *(float2*)(g_y + (size_t)(b * TT + qrow_g) * CC + c)       = v0;
        *(float2*)(g_y + (size_t)(b * TT + qrow_g + 8) * CC + c)   = v1;
    }
}

// ---------------------------------------------------------------------------
// Launch
// ---------------------------------------------------------------------------
extern "C" void kernel_launch(void* const* d_in, const int* in_sizes, int n_in,
                              void* d_out, int out_size) {
    const float* x      = (const float*)d_in[0];
    const float* W_attn = (const float*)d_in[1];
    const float* b_attn = (const float*)d_in[2];
    const float* W_proj = (const float*)d_in[3];
    const float* b_proj = (const float*)d_in[4];
    float* out = (float*)d_out;

    rope_cache_kernel<<<2, 256>>>();

    qkv_gemm_kernel<<<dim3((3 * CC) / 128, BT / 128), 256>>>(x, W_attn, b_attn);

    rope_split_kernel<<<(BB * TT * HH * 32) / 256, 256>>>();

    flash_kernel<<<dim3(TT / 64, BB * HH), 128>>>();

    proj_gemm_kernel<<<dim3(CC / 128, BT / 128), 256>>>(W_proj, b_proj, out);
}